// round 6
// baseline (speedup 1.0000x reference)
#include <cuda_runtime.h>
#include <cuda_bf16.h>

// Batched per-sample MLP: B=32, 1024 -> 2048 (relu) -> 2048 (relu) -> 1024 (linear)
// HBM-bound GEMV chain. Round 5: each CTA covers ALL outputs of its K-chunk
// (256 threads x 8 or 4 outputs), so every CTA streams a perfectly contiguous
// 512KB block of W -> max DRAM row-buffer locality. Split-K + atomicAdd,
// relu folded into consumer staging, bias added by split 0.

#define BATCH 32
#define L0 1024
#define L1 2048
#define L2 2048
#define L3 1024

// Per-sample param layout offsets (fp32 elements)
#define W1_OFF 0LL
#define B1_OFF (W1_OFF + (long long)L0 * L1)          // 2097152
#define W2_OFF (B1_OFF + L1)                          // 2099200
#define B2_OFF (W2_OFF + (long long)L1 * L2)          // 6293504
#define W3_OFF (B2_OFF + L2)                          // 6295552
#define B3_OFF (W3_OFF + (long long)L2 * L3)          // 8392704
#define P_LEN  (B3_OFF + L3)                          // 8393728

// Intermediate activations (device globals — no allocations allowed)
__device__ float g_act1[BATCH * L1];
__device__ float g_act2[BATCH * L2];

// One CTA handles ALL outputs of one (sample, K-chunk): V float4 accumulators
// per thread (V = OUT / (BLOCK*4)). Thread t owns outputs [t*4V, t*4V+4V) —
// warp reads 1024B (V=2) contiguous per row, CTA reads CHUNK*OUT*4 bytes as one
// sequential stream. Partials accumulated into y via atomicAdd.
template <int IN, int OUT, int CHUNK, int BLOCK, bool RELU_IN>
__global__ void __launch_bounds__(BLOCK)
mlp_layer_splitk(const float* __restrict__ params,
                 long long w_off, long long b_off,
                 const float* __restrict__ x_in,
                 float* __restrict__ y_out)
{
    constexpr int V = OUT / (BLOCK * 4);   // float4s per thread (2 or 1)
    __shared__ float sx[CHUNK];

    const int b  = blockIdx.x;
    const int ks = blockIdx.y;
    const int i0 = ks * CHUNK;
    const int o0 = threadIdx.x * (4 * V);  // first output owned by this thread

    // Stage this CTA's input chunk, applying relu if needed.
    const float* __restrict__ xb = x_in + (long long)b * IN + i0;
    for (int i = threadIdx.x; i < CHUNK; i += BLOCK) {
        float v = __ldg(&xb[i]);
        if (RELU_IN) v = fmaxf(v, 0.0f);
        sx[i] = v;
    }
    __syncthreads();

    const float* __restrict__ Wb =
        params + (long long)b * P_LEN + w_off + (long long)i0 * OUT + o0;

    float4 acc[V];
    #pragma unroll
    for (int v = 0; v < V; ++v) acc[v] = make_float4(0.f, 0.f, 0.f, 0.f);

    // First split adds the bias (exactly once per output).
    if (ks == 0) {
        const float* __restrict__ Bv = params + (long long)b * P_LEN + b_off + o0;
        #pragma unroll
        for (int v = 0; v < V; ++v)
            acc[v] = __ldg(reinterpret_cast<const float4*>(Bv) + v);
    }

    // Inner loop: V LDG.128 per thread per row; CTA stream is fully sequential.
    #pragma unroll 4
    for (int i = 0; i < CHUNK; ++i) {
        const float4* __restrict__ row =
            reinterpret_cast<const float4*>(Wb + (long long)i * OUT);
        float s = sx[i];
        #pragma unroll
        for (int v = 0; v < V; ++v) {
            float4 w = __ldg(row + v);
            acc[v].x = fmaf(s, w.x, acc[v].x);
            acc[v].y = fmaf(s, w.y, acc[v].y);
            acc[v].z = fmaf(s, w.z, acc[v].z);
            acc[v].w = fmaf(s, w.w, acc[v].w);
        }
    }

    float* y = y_out + (long long)b * OUT + o0;
    #pragma unroll
    for (int v = 0; v < V; ++v) {
        atomicAdd(y + 4 * v + 0, acc[v].x);
        atomicAdd(y + 4 * v + 1, acc[v].y);
        atomicAdd(y + 4 * v + 2, acc[v].z);
        atomicAdd(y + 4 * v + 3, acc[v].w);
    }
}

extern "C" void kernel_launch(void* const* d_in, const int* in_sizes, int n_in,
                              void* d_out, int out_size)
{
    const float* params = (const float*)d_in[0];  // (B, P) fp32
    const float* x      = (const float*)d_in[1];  // (B, 1024) fp32
    float* out          = (float*)d_out;          // (B, 1024) fp32

    float* act1;
    float* act2;
    cudaGetSymbolAddress((void**)&act1, g_act1);
    cudaGetSymbolAddress((void**)&act2, g_act2);

    // Zero accumulation targets (graph-capturable memset nodes).
    cudaMemsetAsync(act1, 0, sizeof(float) * BATCH * L1);
    cudaMemsetAsync(act2, 0, sizeof(float) * BATCH * L2);
    cudaMemsetAsync(out,  0, sizeof(float) * BATCH * L3);

    // Layer 1: 1024 -> 2048. V=2, chunk 64 -> CTA streams 64*8KB = 512KB.
    // grid (32, 16) = 512 CTAs.
    {
        dim3 grid(BATCH, L0 / 64);
        mlp_layer_splitk<L0, L1, 64, 256, false><<<grid, 256>>>(
            params, W1_OFF, B1_OFF, x, act1);
    }
    // Layer 2: 2048 -> 2048. V=2, chunk 64 -> 512KB/CTA. grid (32, 32) = 1024 CTAs.
    {
        dim3 grid(BATCH, L1 / 64);
        mlp_layer_splitk<L1, L2, 64, 256, true><<<grid, 256>>>(
            params, W2_OFF, B2_OFF, act1, act2);
    }
    // Layer 3: 2048 -> 1024. V=1, chunk 128 -> CTA streams 128*4KB = 512KB.
    // grid (32, 16) = 512 CTAs.
    {
        dim3 grid(BATCH, L2 / 128);
        mlp_layer_splitk<L2, L3, 128, 256, true><<<grid, 256>>>(
            params, W3_OFF, B3_OFF, act2, out);
    }
}

// round 7
// speedup vs baseline: 1.1094x; 1.1094x over previous
#include <cuda_runtime.h>
#include <cuda_bf16.h>

// Batched per-sample MLP: B=32, 1024 -> 2048 (relu) -> 2048 (relu) -> 1024 (linear)
// HBM-bound GEMV chain at the chip LTS/HBM streaming cap (~6.2 TB/s observed).
// Round 6: R4 core (tiled outputs, split-K + atomicAdd, float4 weight loads,
// relu folded into consumer staging) + overhead trim: next layer's accumulator
// is zeroed by the previous layer's ks==0 CTAs, removing 2 of 3 memset nodes.

#define BATCH 32
#define L0 1024
#define L1 2048
#define L2 2048
#define L3 1024

// Per-sample param layout offsets (fp32 elements)
#define W1_OFF 0LL
#define B1_OFF (W1_OFF + (long long)L0 * L1)          // 2097152
#define W2_OFF (B1_OFF + L1)                          // 2099200
#define B2_OFF (W2_OFF + (long long)L1 * L2)          // 6293504
#define W3_OFF (B2_OFF + L2)                          // 6295552
#define B3_OFF (W3_OFF + (long long)L2 * L3)          // 8392704
#define P_LEN  (B3_OFF + L3)                          // 8393728

// Intermediate activations (device globals — no allocations allowed)
__device__ float g_act1[BATCH * L1];
__device__ float g_act2[BATCH * L2];

// One CTA: BLOCK threads, each computing 4 consecutive outputs over a CHUNK of
// the input dimension; partial sums accumulated into y via atomicAdd.
// RELU_IN: apply relu to x_in while staging (x_in holds pre-activation sums).
// ZERO_N: element count of z_buf to zero from ks==0 CTAs (next layer's
// accumulator); kernel boundary orders these stores before the next kernel.
template <int IN, int OUT, int CHUNK, int BLOCK, bool RELU_IN, int ZERO_N>
__global__ void __launch_bounds__(BLOCK)
mlp_layer_splitk(const float* __restrict__ params,
                 long long w_off, long long b_off,
                 const float* __restrict__ x_in,
                 float* __restrict__ y_out,
                 float* __restrict__ z_buf)
{
    __shared__ float sx[CHUNK];

    const int b   = blockIdx.y;
    const int ks  = blockIdx.z;
    const int i0  = ks * CHUNK;
    const int o4  = (blockIdx.x * BLOCK + threadIdx.x) * 4;

    // Side job: ks==0 CTAs zero the next layer's accumulation buffer.
    if (ZERO_N > 0 && ks == 0) {
        constexpr int NTILES = 64;  // gridDim.x * BATCH = 2*32 or 1*32... use y*x
        (void)NTILES;
        const int nzeroers = gridDim.x * BATCH;          // CTAs with ks==0
        const int cta_id   = blockIdx.y * gridDim.x + blockIdx.x;
        float4* zb = reinterpret_cast<float4*>(z_buf);
        const int total4 = ZERO_N / 4;
        for (int idx = cta_id * BLOCK + threadIdx.x; idx < total4;
             idx += nzeroers * BLOCK)
            zb[idx] = make_float4(0.f, 0.f, 0.f, 0.f);
    }

    // Stage this CTA's input chunk, applying relu if needed.
    const float* __restrict__ xb = x_in + (long long)b * IN + i0;
    for (int i = threadIdx.x; i < CHUNK; i += BLOCK) {
        float v = __ldg(&xb[i]);
        if (RELU_IN) v = fmaxf(v, 0.0f);
        sx[i] = v;
    }
    __syncthreads();

    const float* __restrict__ Wb =
        params + (long long)b * P_LEN + w_off + (long long)i0 * OUT + o4;

    float ax = 0.f, ay = 0.f, az = 0.f, aw = 0.f;
    // First split adds the bias (exactly once per output).
    if (ks == 0) {
        const float* __restrict__ Bv = params + (long long)b * P_LEN + b_off + o4;
        float4 bv = __ldg(reinterpret_cast<const float4*>(Bv));
        ax = bv.x; ay = bv.y; az = bv.z; aw = bv.w;
    }

    // Inner loop: one LDG.128 per thread per i (512B/warp), 8-deep unroll for MLP.
    #pragma unroll 8
    for (int i = 0; i < CHUNK; ++i) {
        float4 w = __ldg(reinterpret_cast<const float4*>(Wb + (long long)i * OUT));
        float s = sx[i];
        ax = fmaf(s, w.x, ax);
        ay = fmaf(s, w.y, ay);
        az = fmaf(s, w.z, az);
        aw = fmaf(s, w.w, aw);
    }

    float* y = y_out + (long long)b * OUT + o4;
    atomicAdd(y + 0, ax);
    atomicAdd(y + 1, ay);
    atomicAdd(y + 2, az);
    atomicAdd(y + 3, aw);
}

extern "C" void kernel_launch(void* const* d_in, const int* in_sizes, int n_in,
                              void* d_out, int out_size)
{
    const float* params = (const float*)d_in[0];  // (B, P) fp32
    const float* x      = (const float*)d_in[1];  // (B, 1024) fp32
    float* out          = (float*)d_out;          // (B, 1024) fp32

    float* act1;
    float* act2;
    cudaGetSymbolAddress((void**)&act1, g_act1);
    cudaGetSymbolAddress((void**)&act2, g_act2);

    // Only act1 needs a memset node; act2 / out are zeroed by the preceding
    // layer's ks==0 CTAs (ordered by the kernel boundary).
    cudaMemsetAsync(act1, 0, sizeof(float) * BATCH * L1);

    // Layer 1: 1024 -> 2048. tiles=2, KS=16 (chunk 64) -> 1024 CTAs.
    // ks==0 CTAs also zero act2 (32*2048 floats).
    {
        dim3 grid(L1 / (256 * 4), BATCH, L0 / 64);
        mlp_layer_splitk<L0, L1, 64, 256, false, BATCH * L2><<<grid, 256>>>(
            params, W1_OFF, B1_OFF, x, act1, act2);
    }
    // Layer 2: 2048 -> 2048. tiles=2, KS=16 (chunk 128) -> 1024 CTAs. relu on read.
    // ks==0 CTAs also zero out (32*1024 floats).
    {
        dim3 grid(L2 / (256 * 4), BATCH, L1 / 128);
        mlp_layer_splitk<L1, L2, 128, 256, true, BATCH * L3><<<grid, 256>>>(
            params, W2_OFF, B2_OFF, act1, act2, out);
    }
    // Layer 3: 2048 -> 1024. tiles=1, KS=32 (chunk 64) -> 1024 CTAs. relu on read.
    {
        dim3 grid(L3 / (256 * 4), BATCH, L2 / 64);
        mlp_layer_splitk<L2, L3, 64, 256, true, 0><<<grid, 256>>>(
            params, W3_OFF, B3_OFF, act2, out, nullptr);
    }
}

// round 8
// speedup vs baseline: 1.1217x; 1.0110x over previous
#include <cuda_runtime.h>
#include <cuda_bf16.h>

// Batched per-sample MLP: B=32, 1024 -> 2048 (relu) -> 2048 (relu) -> 1024 (linear)
// HBM-bound GEMV chain at the achievable streaming ceiling (~6.1 TB/s per kernel).
// Round 7: remove ALL memset nodes (layer3 re-zeros act1 post-sync for the next
// graph replay) and chain the 3 layers with Programmatic Dependent Launch so
// successor CTAs launch during the predecessor's drain wave. Streaming core
// (tiled outputs, split-K + atomicAdd, float4 W loads, relu-on-read) unchanged.

#define BATCH 32
#define L0 1024
#define L1 2048
#define L2 2048
#define L3 1024

// Per-sample param layout offsets (fp32 elements)
#define W1_OFF 0LL
#define B1_OFF (W1_OFF + (long long)L0 * L1)          // 2097152
#define W2_OFF (B1_OFF + L1)                          // 2099200
#define B2_OFF (W2_OFF + (long long)L1 * L2)          // 6293504
#define W3_OFF (B2_OFF + L2)                          // 6295552
#define B3_OFF (W3_OFF + (long long)L2 * L3)          // 8392704
#define P_LEN  (B3_OFF + L3)                          // 8393728

// Intermediate activations (device globals — zero-initialized at load,
// re-zeroed each pass for graph replay correctness).
__device__ float g_act1[BATCH * L1];
__device__ float g_act2[BATCH * L2];

// One CTA: BLOCK threads, each computing 4 consecutive outputs over a CHUNK of
// the input dimension; partial sums accumulated into y via atomicAdd.
// RELU_IN : apply relu to x_in while staging (x_in holds pre-activation sums).
// ZERO_N  : element count of z_buf for ks==0 CTAs to zero.
// PDL     : call cudaGridDependencySynchronize() before touching x_in.
// ZERO_POST: zero z_buf AFTER the dependency sync (z_buf is read by the
//            predecessor, so the zero must wait for it — layer3 zeroing act1).
template <int IN, int OUT, int CHUNK, int BLOCK, bool RELU_IN, int ZERO_N,
          bool PDL, bool ZERO_POST>
__global__ void __launch_bounds__(BLOCK)
mlp_layer_splitk(const float* __restrict__ params,
                 long long w_off, long long b_off,
                 const float* __restrict__ x_in,
                 float* __restrict__ y_out,
                 float* __restrict__ z_buf)
{
    __shared__ float sx[CHUNK];

    const int b   = blockIdx.y;
    const int ks  = blockIdx.z;
    const int i0  = ks * CHUNK;
    const int o4  = (blockIdx.x * BLOCK + threadIdx.x) * 4;

    const int nzeroers = gridDim.x * BATCH;
    const int cta_id   = blockIdx.y * gridDim.x + blockIdx.x;

    // Pre-sync side job: zero a buffer the predecessor does NOT read
    // (runs during the predecessor's drain wave under PDL).
    if (ZERO_N > 0 && !ZERO_POST && ks == 0) {
        float4* zb = reinterpret_cast<float4*>(z_buf);
        const int total4 = ZERO_N / 4;
        for (int idx = cta_id * BLOCK + threadIdx.x; idx < total4;
             idx += nzeroers * BLOCK)
            zb[idx] = make_float4(0.f, 0.f, 0.f, 0.f);
    }

    // Pre-sync: bias prefetch (pure input, independent of predecessor).
    float ax = 0.f, ay = 0.f, az = 0.f, aw = 0.f;
    if (ks == 0) {
        const float* __restrict__ Bv = params + (long long)b * P_LEN + b_off + o4;
        float4 bv = __ldg(reinterpret_cast<const float4*>(Bv));
        ax = bv.x; ay = bv.y; az = bv.z; aw = bv.w;
    }

#if defined(__CUDA_ARCH__) && (__CUDA_ARCH__ >= 900)
    if (PDL) cudaGridDependencySynchronize();
#endif

    // Post-sync zero job (buffer was read by the predecessor; sync makes it safe).
    if (ZERO_N > 0 && ZERO_POST && ks == 0) {
        float4* zb = reinterpret_cast<float4*>(z_buf);
        const int total4 = ZERO_N / 4;
        for (int idx = cta_id * BLOCK + threadIdx.x; idx < total4;
             idx += nzeroers * BLOCK)
            zb[idx] = make_float4(0.f, 0.f, 0.f, 0.f);
    }

    // Stage this CTA's input chunk, applying relu if needed.
    const float* __restrict__ xb = x_in + (long long)b * IN + i0;
    for (int i = threadIdx.x; i < CHUNK; i += BLOCK) {
        float v = __ldg(&xb[i]);
        if (RELU_IN) v = fmaxf(v, 0.0f);
        sx[i] = v;
    }
    __syncthreads();

    const float* __restrict__ Wb =
        params + (long long)b * P_LEN + w_off + (long long)i0 * OUT + o4;

    // Inner loop: one LDG.128 per thread per i (512B/warp), 8-deep unroll for MLP.
    #pragma unroll 8
    for (int i = 0; i < CHUNK; ++i) {
        float4 w = __ldg(reinterpret_cast<const float4*>(Wb + (long long)i * OUT));
        float s = sx[i];
        ax = fmaf(s, w.x, ax);
        ay = fmaf(s, w.y, ay);
        az = fmaf(s, w.z, az);
        aw = fmaf(s, w.w, aw);
    }

    float* y = y_out + (long long)b * OUT + o4;
    atomicAdd(y + 0, ax);
    atomicAdd(y + 1, ay);
    atomicAdd(y + 2, az);
    atomicAdd(y + 3, aw);

#if defined(__CUDA_ARCH__) && (__CUDA_ARCH__ >= 900)
    // Let the dependent kernel launch as soon as all CTAs reach here.
    cudaTriggerProgrammaticLaunchCompletion();
#endif
}

extern "C" void kernel_launch(void* const* d_in, const int* in_sizes, int n_in,
                              void* d_out, int out_size)
{
    const float* params = (const float*)d_in[0];  // (B, P) fp32
    const float* x      = (const float*)d_in[1];  // (B, 1024) fp32
    float* out          = (float*)d_out;          // (B, 1024) fp32

    float* act1;
    float* act2;
    cudaGetSymbolAddress((void**)&act1, g_act1);
    cudaGetSymbolAddress((void**)&act2, g_act2);

    // No memsets: act1/act2 are zero at load and re-zeroed each pass
    // (layer3 zeroes act1 post-sync, layer1 zeroes act2, layer2 zeroes out).

    cudaLaunchAttribute pdl_attr[1];
    pdl_attr[0].id = cudaLaunchAttributeProgrammaticStreamSerialization;
    pdl_attr[0].val.programmaticStreamSerializationAllowed = 1;

    // Layer 1: 1024 -> 2048. tiles=2, KS=16 (chunk 64) -> 1024 CTAs.
    // ks==0 CTAs also zero act2. No PDL (first kernel).
    {
        dim3 grid(L1 / (256 * 4), BATCH, L0 / 64);
        auto kfn = mlp_layer_splitk<L0, L1, 64, 256, false, BATCH * L2, false, false>;
        kfn<<<grid, 256>>>(params, W1_OFF, B1_OFF, x, act1, act2);
    }
    // Layer 2: 2048 -> 2048. tiles=2, KS=16 (chunk 128) -> 1024 CTAs. relu on read.
    // ks==0 CTAs zero `out` pre-sync. PDL on layer 1.
    {
        cudaLaunchConfig_t cfg = {};
        cfg.gridDim  = dim3(L2 / (256 * 4), BATCH, L1 / 128);
        cfg.blockDim = dim3(256, 1, 1);
        cfg.attrs = pdl_attr;
        cfg.numAttrs = 1;
        auto kfn = mlp_layer_splitk<L1, L2, 128, 256, true, BATCH * L3, true, false>;
        cudaLaunchKernelEx(&cfg, kfn, params, W2_OFF, B2_OFF,
                           (const float*)act1, act2, out);
    }
    // Layer 3: 2048 -> 1024. tiles=1, KS=32 (chunk 64) -> 1024 CTAs. relu on read.
    // ks==0 CTAs zero act1 POST-sync (act1 is read by layer 2). PDL on layer 2.
    {
        cudaLaunchConfig_t cfg = {};
        cfg.gridDim  = dim3(L3 / (256 * 4), BATCH, L2 / 64);
        cfg.blockDim = dim3(256, 1, 1);
        cfg.attrs = pdl_attr;
        cfg.numAttrs = 1;
        auto kfn = mlp_layer_splitk<L2, L3, 64, 256, true, BATCH * L1, true, true>;
        cudaLaunchKernelEx(&cfg, kfn, params, W3_OFF, B3_OFF,
                           (const float*)act2, out, act1);
    }
}